// round 1
// baseline (speedup 1.0000x reference)
#include <cuda_runtime.h>
#include <math.h>

#define Bsz 8
#define Cc 1024
#define Ll 1024
#define Hh 16
#define Dk 64
#define NBH (Bsz*Hh)
#define SCALE 0.125f

// Scratch (allocation-free rule: __device__ globals)
__device__ float g_qh[Bsz*Cc*Ll];                    // 32 MB
__device__ float g_kh[Bsz*Cc*Ll];                    // 32 MB
__device__ float g_vh[Bsz*Cc*Ll];                    // 32 MB
__device__ float g_sc[(size_t)NBH*Ll*Ll];            // 512 MB: scores [bh][t][s]
__device__ float g_m [NBH*Ll];                       // per-(bh,s) max over t
__device__ float g_rz[NBH*Ll];                       // per-(bh,s) 1/sum

// ---------------------------------------------------------------------------
// Kernel 1: projection  Y[b,o,l] = sum_c W[o,c] X[b,c,l] + bias[o]
// 128x128 tile, BK=8, 256 threads, 8x8 per thread.
// ---------------------------------------------------------------------------
__global__ __launch_bounds__(256) void proj_kernel(const float* __restrict__ X,
                                                   const float* __restrict__ W,
                                                   const float* __restrict__ bias,
                                                   int which)
{
    float* Y = (which == 0) ? g_qh : ((which == 1) ? g_kh : g_vh);
    const int b  = blockIdx.z;
    const float* Xb = X + (size_t)b * Cc * Ll;
    float*       Yb = Y + (size_t)b * Cc * Ll;
    const int o0 = blockIdx.y * 128;
    const int l0 = blockIdx.x * 128;

    __shared__ float As[8][128];   // [c][o]
    __shared__ float Bs[8][128];   // [c][l]

    const int tid = threadIdx.x;
    const int tx = tid & 15, ty = tid >> 4;

    float acc[8][8] = {};

    const int arow = tid >> 1, acg = (tid & 1) * 4;        // W tile: 128 o x 8 c
    const int brow = tid >> 5, bcol = (tid & 31) * 4;      // X tile: 8 c x 128 l

    for (int c0 = 0; c0 < Cc; c0 += 8) {
        float4 a = *(const float4*)(W + (size_t)(o0 + arow) * Cc + c0 + acg);
        As[acg + 0][arow] = a.x;
        As[acg + 1][arow] = a.y;
        As[acg + 2][arow] = a.z;
        As[acg + 3][arow] = a.w;
        *(float4*)&Bs[brow][bcol] =
            *(const float4*)(Xb + (size_t)(c0 + brow) * Ll + l0 + bcol);
        __syncthreads();

        #pragma unroll
        for (int kc = 0; kc < 8; kc++) {
            float ra[8], rb[8];
            #pragma unroll
            for (int i = 0; i < 8; i++) ra[i] = As[kc][ty * 8 + i];
            #pragma unroll
            for (int j = 0; j < 8; j++) rb[j] = Bs[kc][tx * 8 + j];
            #pragma unroll
            for (int i = 0; i < 8; i++)
                #pragma unroll
                for (int j = 0; j < 8; j++)
                    acc[i][j] = fmaf(ra[i], rb[j], acc[i][j]);
        }
        __syncthreads();
    }

    #pragma unroll
    for (int i = 0; i < 8; i++) {
        const float bi = bias[o0 + ty * 8 + i];
        float* yrow = Yb + (size_t)(o0 + ty * 8 + i) * Ll + l0 + tx * 8;
        float4 v0 = make_float4(acc[i][0] + bi, acc[i][1] + bi,
                                acc[i][2] + bi, acc[i][3] + bi);
        float4 v1 = make_float4(acc[i][4] + bi, acc[i][5] + bi,
                                acc[i][6] + bi, acc[i][7] + bi);
        *(float4*)yrow       = v0;
        *(float4*)(yrow + 4) = v1;
    }
}

// ---------------------------------------------------------------------------
// Kernel 2: scores  S[bh,t,s] = SCALE * sum_c qh[bh,c,t] kh[bh,c,s]
// Both operands K-major (c stride = L). 128x128 tile, K=64 in chunks of 8.
// ---------------------------------------------------------------------------
__global__ __launch_bounds__(256) void scores_kernel()
{
    const int bh = blockIdx.z;
    const int b = bh >> 4, h = bh & 15;
    const float* Qb = g_qh + ((size_t)b * Cc + h * Dk) * Ll;
    const float* Kb = g_kh + ((size_t)b * Cc + h * Dk) * Ll;
    float*       Sb = g_sc + (size_t)bh * Ll * Ll;
    const int t0 = blockIdx.y * 128;
    const int s0 = blockIdx.x * 128;

    __shared__ float As[8][128];   // [c][t]
    __shared__ float Bs[8][128];   // [c][s]

    const int tid = threadIdx.x;
    const int tx = tid & 15, ty = tid >> 4;
    const int row = tid >> 5, col = (tid & 31) * 4;

    float acc[8][8] = {};

    for (int c0 = 0; c0 < Dk; c0 += 8) {
        *(float4*)&As[row][col] =
            *(const float4*)(Qb + (size_t)(c0 + row) * Ll + t0 + col);
        *(float4*)&Bs[row][col] =
            *(const float4*)(Kb + (size_t)(c0 + row) * Ll + s0 + col);
        __syncthreads();

        #pragma unroll
        for (int kc = 0; kc < 8; kc++) {
            float ra[8], rb[8];
            #pragma unroll
            for (int i = 0; i < 8; i++) ra[i] = As[kc][ty * 8 + i];
            #pragma unroll
            for (int j = 0; j < 8; j++) rb[j] = Bs[kc][tx * 8 + j];
            #pragma unroll
            for (int i = 0; i < 8; i++)
                #pragma unroll
                for (int j = 0; j < 8; j++)
                    acc[i][j] = fmaf(ra[i], rb[j], acc[i][j]);
        }
        __syncthreads();
    }

    #pragma unroll
    for (int i = 0; i < 8; i++) {
        float* srow = Sb + (size_t)(t0 + ty * 8 + i) * Ll + s0 + tx * 8;
        float4 v0 = make_float4(acc[i][0] * SCALE, acc[i][1] * SCALE,
                                acc[i][2] * SCALE, acc[i][3] * SCALE);
        float4 v1 = make_float4(acc[i][4] * SCALE, acc[i][5] * SCALE,
                                acc[i][6] * SCALE, acc[i][7] * SCALE);
        *(float4*)srow       = v0;
        *(float4*)(srow + 4) = v1;
    }
}

// ---------------------------------------------------------------------------
// Kernel 3: per-(bh,s) column softmax stats over t (online, one pass).
// Thread = one s column; warp reads 32 consecutive s at fixed t (coalesced).
// ---------------------------------------------------------------------------
__global__ __launch_bounds__(256) void stats_kernel()
{
    const int bh = blockIdx.y;
    const int s = blockIdx.x * 256 + threadIdx.x;
    const float* Sp = g_sc + (size_t)bh * Ll * Ll + s;

    float m = -1e30f, z = 0.f;
    #pragma unroll 4
    for (int t = 0; t < Ll; t++) {
        float x = Sp[(size_t)t * Ll];
        if (x > m) { z = z * __expf(m - x) + 1.f; m = x; }
        else       { z += __expf(x - m); }
    }
    g_m [bh * Ll + s] = m;
    g_rz[bh * Ll + s] = 1.f / z;
}

// ---------------------------------------------------------------------------
// Kernel 4: out[bh,c,t] = sum_s exp(S[t,s]-m[s])*rz[s] * v[bh,c,s]
// Attn never materialized: exp applied on the fly while staging P[s][t] tiles.
// Tile: 64(c) x 128(t), BK=16(s), 256 threads, 4x8 per thread.
// ---------------------------------------------------------------------------
__global__ __launch_bounds__(256) void out_kernel(float* __restrict__ out)
{
    const int bh = blockIdx.y;
    const int b = bh >> 4, h = bh & 15;
    const int t0 = blockIdx.x * 128;

    const float* Vb = g_vh + ((size_t)b * Cc + h * Dk) * Ll;
    const float* Sb = g_sc + (size_t)bh * Ll * Ll;
    const float* mp = g_m  + bh * Ll;
    const float* rp = g_rz + bh * Ll;

    __shared__ float Vs[16][64];    // [s][c]
    __shared__ float Ps[16][128];   // [s][t]

    const int tid = threadIdx.x;
    const int tx = tid & 15, ty = tid >> 4;

    const int vc = tid >> 2, vsg = (tid & 3) * 4;   // V tile loader
    const int pt = tid >> 1, psg = (tid & 1) * 8;   // P tile loader

    float acc[4][8] = {};

    for (int s0 = 0; s0 < Ll; s0 += 16) {
        float4 vv = *(const float4*)(Vb + (size_t)vc * Ll + s0 + vsg);
        Vs[vsg + 0][vc] = vv.x;
        Vs[vsg + 1][vc] = vv.y;
        Vs[vsg + 2][vc] = vv.z;
        Vs[vsg + 3][vc] = vv.w;

        #pragma unroll
        for (int k = 0; k < 8; k += 4) {
            float4 sv = *(const float4*)(Sb + (size_t)(t0 + pt) * Ll + s0 + psg + k);
            float xs[4] = {sv.x, sv.y, sv.z, sv.w};
            #pragma unroll
            for (int u = 0; u < 4; u++) {
                const int si = s0 + psg + k + u;
                Ps[psg + k + u][pt] = __expf(xs[u] - mp[si]) * rp[si];
            }
        }
        __syncthreads();

        #pragma unroll
        for (int ks = 0; ks < 16; ks++) {
            float ra[4], rb[8];
            #pragma unroll
            for (int i = 0; i < 4; i++) ra[i] = Vs[ks][ty * 4 + i];
            #pragma unroll
            for (int j = 0; j < 8; j++) rb[j] = Ps[ks][tx * 8 + j];
            #pragma unroll
            for (int i = 0; i < 4; i++)
                #pragma unroll
                for (int j = 0; j < 8; j++)
                    acc[i][j] = fmaf(ra[i], rb[j], acc[i][j]);
        }
        __syncthreads();
    }

    float* ob = out + ((size_t)b * Cc + h * Dk) * Ll;
    #pragma unroll
    for (int i = 0; i < 4; i++) {
        float* orow = ob + (size_t)(ty * 4 + i) * Ll + t0 + tx * 8;
        float4 v0 = make_float4(acc[i][0], acc[i][1], acc[i][2], acc[i][3]);
        float4 v1 = make_float4(acc[i][4], acc[i][5], acc[i][6], acc[i][7]);
        *(float4*)orow       = v0;
        *(float4*)(orow + 4) = v1;
    }
}

// ---------------------------------------------------------------------------
extern "C" void kernel_launch(void* const* d_in, const int* in_sizes, int n_in,
                              void* d_out, int out_size)
{
    const float* q  = (const float*)d_in[0];
    const float* k  = (const float*)d_in[1];
    const float* v  = (const float*)d_in[2];
    const float* Wq = (const float*)d_in[3];
    const float* bq = (const float*)d_in[4];
    const float* Wk = (const float*)d_in[5];
    const float* bk = (const float*)d_in[6];
    const float* Wv = (const float*)d_in[7];
    const float* bv = (const float*)d_in[8];
    float* out = (float*)d_out;

    dim3 gp(Ll / 128, Cc / 128, Bsz);          // 8,8,8
    proj_kernel<<<gp, 256>>>(q, Wq, bq, 0);
    proj_kernel<<<gp, 256>>>(k, Wk, bk, 1);
    proj_kernel<<<gp, 256>>>(v, Wv, bv, 2);

    scores_kernel<<<dim3(Ll / 128, Ll / 128, NBH), 256>>>();   // 8,8,128
    stats_kernel <<<dim3(Ll / 256, NBH), 256>>>();             // 4,128
    out_kernel   <<<dim3(Ll / 128, NBH), 256>>>(out);          // 8,128
}

// round 5
// speedup vs baseline: 1.8632x; 1.8632x over previous
#include <cuda_runtime.h>
#include <cuda_fp16.h>
#include <math.h>
#include <stdint.h>

#define Bsz 8
#define Cc 1024
#define Ll 1024
#define Hh 16
#define Dk 64
#define NBH (Bsz*Hh)
#define SCALE 0.125f

// ---------------------------------------------------------------------------
// Scratch (__device__ globals; no allocations allowed)
// ---------------------------------------------------------------------------
__device__ __half g_Whi[3][Cc*Cc];
__device__ __half g_Wlo[3][Cc*Cc];
__device__ __half g_xThi[(size_t)Bsz*Ll*Cc];   // [b][l][c]
__device__ __half g_xTlo[(size_t)Bsz*Ll*Cc];
__device__ __half g_qhi[(size_t)NBH*Ll*Dk];    // [bh][t][dk]
__device__ __half g_qlo[(size_t)NBH*Ll*Dk];
__device__ __half g_khi[(size_t)NBH*Ll*Dk];    // [bh][s][dk]
__device__ __half g_klo[(size_t)NBH*Ll*Dk];
__device__ __half g_vhi[(size_t)NBH*Dk*Ll];    // [bh][dk][s]
__device__ __half g_vlo[(size_t)NBH*Dk*Ll];
__device__ float  g_sc[(size_t)NBH*Ll*Ll];     // 512 MB scores [bh][t][s]
__device__ float  g_m [NBH*Ll];
__device__ float  g_rz[NBH*Ll];

#define SW128(o) ((uint32_t)(o) ^ ((((uint32_t)(o)) >> 3) & 0x70))

__device__ __forceinline__ uint32_t smem_u32(const void* p) {
    uint32_t a;
    asm("{ .reg .u64 t; cvta.to.shared.u64 t, %1; cvt.u32.u64 %0, t; }" : "=r"(a) : "l"(p));
    return a;
}
__device__ __forceinline__ void ldsm4(uint32_t* r, uint32_t addr) {
    asm volatile("ldmatrix.sync.aligned.m8n8.x4.shared.b16 {%0,%1,%2,%3}, [%4];"
                 : "=r"(r[0]), "=r"(r[1]), "=r"(r[2]), "=r"(r[3]) : "r"(addr));
}
__device__ __forceinline__ void mma16816(float* d, const uint32_t* a, const uint32_t* b) {
    asm volatile(
        "mma.sync.aligned.m16n8k16.row.col.f32.f16.f16.f32 "
        "{%0,%1,%2,%3}, {%4,%5,%6,%7}, {%8,%9}, {%0,%1,%2,%3};"
        : "+f"(d[0]), "+f"(d[1]), "+f"(d[2]), "+f"(d[3])
        : "r"(a[0]), "r"(a[1]), "r"(a[2]), "r"(a[3]), "r"(b[0]), "r"(b[1]));
}

// Load ROWS x 64 halfs (128B rows) into SW128-swizzled smem. 256 threads.
template <int ROWS>
__device__ __forceinline__ void load_tile256(char* dst, const __half* src,
                                             int stride_h, int tid) {
    #pragma unroll
    for (int i = 0; i < ROWS * 8 / 256; i++) {
        int idx = i * 256 + tid;
        int r = idx >> 3, cb = (idx & 7) * 16;
        uint4 v = *(const uint4*)((const char*)(src + (size_t)r * stride_h) + cb);
        *(uint4*)(dst + SW128(r * 128 + cb)) = v;
    }
}

// One K=64 chunk of split-fp16 GEMM: acc += Ahi*Bhi + Alo*Bhi + Ahi*Blo.
// A tile: rows=m (k-major 64), B tile: rows=n (k-major 64). SW128 smem.
template <int MF, int NF>
__device__ __forceinline__ void gemm_chunk(uint32_t saHi, uint32_t saLo,
                                           uint32_t sbHi, uint32_t sbLo,
                                           int m0, int n0, int lane,
                                           float acc[MF][NF][4]) {
    const int arow = lane & 15,                 acol8 = (lane >> 4) * 8;
    const int brow = (lane >> 4) * 8 + (lane & 7), bcol8 = ((lane >> 3) & 1) * 8;
    #pragma unroll
    for (int ks = 0; ks < 4; ks++) {
        const int k0 = ks * 16;
        uint32_t ahi[MF][4], alo[MF][4];
        #pragma unroll
        for (int mf = 0; mf < MF; mf++) {
            uint32_t off = SW128((m0 + mf * 16 + arow) * 128 + (k0 + acol8) * 2);
            ldsm4(ahi[mf], saHi + off);
            ldsm4(alo[mf], saLo + off);
        }
        uint32_t bhi[NF][2], blo[NF][2];
        #pragma unroll
        for (int p = 0; p < NF / 2; p++) {
            uint32_t off = SW128((n0 + p * 16 + brow) * 128 + (k0 + bcol8) * 2);
            uint32_t r[4];
            ldsm4(r, sbHi + off);
            bhi[p*2][0] = r[0]; bhi[p*2][1] = r[1];
            bhi[p*2+1][0] = r[2]; bhi[p*2+1][1] = r[3];
            ldsm4(r, sbLo + off);
            blo[p*2][0] = r[0]; blo[p*2][1] = r[1];
            blo[p*2+1][0] = r[2]; blo[p*2+1][1] = r[3];
        }
        #pragma unroll
        for (int mf = 0; mf < MF; mf++)
            #pragma unroll
            for (int nf = 0; nf < NF; nf++) {
                mma16816(acc[mf][nf], ahi[mf], bhi[nf]);
                mma16816(acc[mf][nf], alo[mf], bhi[nf]);
                mma16816(acc[mf][nf], ahi[mf], blo[nf]);
            }
    }
}

// ---------------------------------------------------------------------------
// Conversions
// ---------------------------------------------------------------------------
__global__ __launch_bounds__(256) void conv_w_kernel(const float* __restrict__ W, int which) {
    int i = (blockIdx.x * 256 + threadIdx.x) * 4;
    float4 v = *(const float4*)(W + i);
    float xs[4] = {v.x, v.y, v.z, v.w};
    __half hi[4], lo[4];
    #pragma unroll
    for (int j = 0; j < 4; j++) {
        hi[j] = __float2half_rn(xs[j]);
        lo[j] = __float2half_rn(xs[j] - __half2float(hi[j]));
    }
    __half2* H = (__half2*)(g_Whi[which] + i);
    __half2* L = (__half2*)(g_Wlo[which] + i);
    H[0] = __halves2half2(hi[0], hi[1]); H[1] = __halves2half2(hi[2], hi[3]);
    L[0] = __halves2half2(lo[0], lo[1]); L[1] = __halves2half2(lo[2], lo[3]);
}

__global__ __launch_bounds__(256) void conv_xt_kernel(const float* __restrict__ x) {
    __shared__ float tile[32][33];
    const int b = blockIdx.z, c0 = blockIdx.y * 32, l0 = blockIdx.x * 32;
    const int tx = threadIdx.x, ty = threadIdx.y;
    const float* xb = x + (size_t)b * Cc * Ll;
    #pragma unroll
    for (int i = 0; i < 4; i++)
        tile[ty + i * 8][tx] = xb[(size_t)(c0 + ty + i * 8) * Ll + l0 + tx];
    __syncthreads();
    #pragma unroll
    for (int i = 0; i < 4; i++) {
        float vv = tile[tx][ty + i * 8];
        __half hi = __float2half_rn(vv);
        __half lo = __float2half_rn(vv - __half2float(hi));
        size_t o = (size_t)b * Ll * Cc + (size_t)(l0 + ty + i * 8) * Cc + c0 + tx;
        g_xThi[o] = hi;
        g_xTlo[o] = lo;
    }
}

// ---------------------------------------------------------------------------
// Projection: Y[o,l] = sum_c W[o,c] xT[l,c] + bias[o]; split-fp16 outputs.
// Block tile 128(o) x 128(l); 8 warps (4m x 2n); warp tile 32x64.
// ---------------------------------------------------------------------------
__global__ __launch_bounds__(256) void proj_mma(const float* __restrict__ bias, int which) {
    extern __shared__ char smem[];
    const int AH = 0, AL = 16384, BH = 32768, BL = 49152;
    uint32_t sb = smem_u32(smem);
    const int tid = threadIdx.x, w = tid >> 5, lane = tid & 31;
    const int wm = w >> 1, wn = w & 1;
    const int b = blockIdx.z, o0 = blockIdx.y * 128, l0 = blockIdx.x * 128;

    const __half* Whi = g_Whi[which] + (size_t)o0 * Cc;
    const __half* Wlo = g_Wlo[which] + (size_t)o0 * Cc;
    const __half* Xhi = g_xThi + (size_t)b * Ll * Cc + (size_t)l0 * Cc;
    const __half* Xlo = g_xTlo + (size_t)b * Ll * Cc + (size_t)l0 * Cc;

    float acc[2][8][4] = {};
    for (int c0 = 0; c0 < Cc; c0 += 64) {
        load_tile256<128>(smem + AH, Whi + c0, Cc, tid);
        load_tile256<128>(smem + AL, Wlo + c0, Cc, tid);
        load_tile256<128>(smem + BH, Xhi + c0, Cc, tid);
        load_tile256<128>(smem + BL, Xlo + c0, Cc, tid);
        __syncthreads();
        gemm_chunk<2, 8>(sb + AH, sb + AL, sb + BH, sb + BL,
                         wm * 32, wn * 64, lane, acc);
        __syncthreads();
    }

    const int gid = lane >> 2, tid4 = lane & 3;
    #pragma unroll
    for (int mf = 0; mf < 2; mf++) {
        #pragma unroll
        for (int h2 = 0; h2 < 2; h2++) {
            const int o = o0 + wm * 32 + mf * 16 + gid + h2 * 8;
            const float bi = bias[o];
            const int hh = o >> 6, dk = o & 63;
            #pragma unroll
            for (int nf = 0; nf < 8; nf++) {
                const int l = l0 + wn * 64 + nf * 8 + tid4 * 2;
                float v0 = acc[mf][nf][h2 * 2 + 0] + bi;
                float v1 = acc[mf][nf][h2 * 2 + 1] + bi;
                __half hi0 = __float2half_rn(v0);
                __half lo0 = __float2half_rn(v0 - __half2float(hi0));
                __half hi1 = __float2half_rn(v1);
                __half lo1 = __float2half_rn(v1 - __half2float(hi1));
                if (which < 2) {
                    __half* Hp = (which == 0 ? g_qhi : g_khi);
                    __half* Lp = (which == 0 ? g_qlo : g_klo);
                    size_t off = ((size_t)(b * Hh + hh) * Ll + l) * Dk + dk;
                    Hp[off] = hi0; Hp[off + Dk] = hi1;
                    Lp[off] = lo0; Lp[off + Dk] = lo1;
                } else {
                    size_t off = ((size_t)(b * Hh + hh) * Dk + dk) * Ll + l;
                    *(__half2*)(g_vhi + off) = __halves2half2(hi0, hi1);
                    *(__half2*)(g_vlo + off) = __halves2half2(lo0, lo1);
                }
            }
        }
    }
}

// ---------------------------------------------------------------------------
// Scores: S[t,s] = SCALE * sum_c Q[t,c] K[s,c].  Block 128t x 128s, K=64.
// ---------------------------------------------------------------------------
__global__ __launch_bounds__(256) void scores_mma() {
    extern __shared__ char smem[];
    const int AH = 0, AL = 16384, BH = 32768, BL = 49152;
    uint32_t sb = smem_u32(smem);
    const int tid = threadIdx.x, w = tid >> 5, lane = tid & 31;
    const int wm = w >> 1, wn = w & 1;
    const int bh = blockIdx.z, t0 = blockIdx.y * 128, s0 = blockIdx.x * 128;

    load_tile256<128>(smem + AH, g_qhi + ((size_t)bh * Ll + t0) * Dk, Dk, tid);
    load_tile256<128>(smem + AL, g_qlo + ((size_t)bh * Ll + t0) * Dk, Dk, tid);
    load_tile256<128>(smem + BH, g_khi + ((size_t)bh * Ll + s0) * Dk, Dk, tid);
    load_tile256<128>(smem + BL, g_klo + ((size_t)bh * Ll + s0) * Dk, Dk, tid);
    __syncthreads();

    float acc[2][8][4] = {};
    gemm_chunk<2, 8>(sb + AH, sb + AL, sb + BH, sb + BL,
                     wm * 32, wn * 64, lane, acc);

    float* Sb = g_sc + (size_t)bh * Ll * Ll;
    const int gid = lane >> 2, tid4 = lane & 3;
    #pragma unroll
    for (int mf = 0; mf < 2; mf++)
        #pragma unroll
        for (int h2 = 0; h2 < 2; h2++) {
            const int t = t0 + wm * 32 + mf * 16 + gid + h2 * 8;
            float* rowp = Sb + (size_t)t * Ll;
            #pragma unroll
            for (int nf = 0; nf < 8; nf++) {
                const int s = s0 + wn * 64 + nf * 8 + tid4 * 2;
                float2 vv = make_float2(acc[mf][nf][h2 * 2] * SCALE,
                                        acc[mf][nf][h2 * 2 + 1] * SCALE);
                *(float2*)(rowp + s) = vv;
            }
        }
}

// ---------------------------------------------------------------------------
// Stats: per-(bh,s) online max & 1/sum over t.
// ---------------------------------------------------------------------------
__global__ __launch_bounds__(256) void stats_kernel() {
    const int bh = blockIdx.y;
    const int s = blockIdx.x * 256 + threadIdx.x;
    const float* Sp = g_sc + (size_t)bh * Ll * Ll + s;
    float m = -1e30f, z = 0.f;
    #pragma unroll 4
    for (int t = 0; t < Ll; t++) {
        float x = Sp[(size_t)t * Ll];
        if (x > m) { z = z * __expf(m - x) + 1.f; m = x; }
        else       { z += __expf(x - m); }
    }
    g_m [bh * Ll + s] = m;
    g_rz[bh * Ll + s] = 1.f / z;
}

// ---------------------------------------------------------------------------
// Output: out[c,t] = sum_s P[t,s] V[c,s], P = exp(S-m)*rz built on the fly.
// Block 64(c) x 128(t); 8 warps (2m x 4n); warp tile 32x32; K loop over s.
// ---------------------------------------------------------------------------
__global__ __launch_bounds__(256) void out_mma(float* __restrict__ out) {
    extern __shared__ char smem[];
    const int PH = 0, PL = 16384, VH = 32768, VL = 40960, MOF = 49152, ROF = 53248;
    uint32_t sb = smem_u32(smem);
    const int tid = threadIdx.x, w = tid >> 5, lane = tid & 31;
    const int wm = w >> 2, wn = w & 3;
    const int bh = blockIdx.y, t0 = blockIdx.x * 128;

    float* ms = (float*)(smem + MOF);
    float* rs = (float*)(smem + ROF);
    for (int i = tid; i < Ll; i += 256) {
        ms[i] = g_m [bh * Ll + i];
        rs[i] = g_rz[bh * Ll + i];
    }
    __syncthreads();

    const float* Sp = g_sc + (size_t)bh * Ll * Ll + (size_t)t0 * Ll;
    const __half* Vh = g_vhi + (size_t)bh * Dk * Ll;
    const __half* Vl = g_vlo + (size_t)bh * Dk * Ll;

    float acc[2][4][4] = {};
    for (int s0 = 0; s0 < Ll; s0 += 64) {
        // Build P tile (128t x 64s): exp + normalize, split fp16, swizzled.
        #pragma unroll
        for (int i = 0; i < 8; i++) {
            int idx = i * 256 + tid;
            int t = idx >> 4, sq = (idx & 15) * 4;
            float4 x = *(const float4*)(Sp + (size_t)t * Ll + s0 + sq);
            float xs[4] = {x.x, x.y, x.z, x.w};
            __half hi[4], lo[4];
            #pragma unroll
            for (int j = 0; j < 4; j++) {
                int si = s0 + sq + j;
                float p = __expf(xs[j] - ms[si]) * rs[si];
                hi[j] = __float2half_rn(p);
                lo[j] = __float2half_rn(p - __half2float(hi[j]));
            }
            uint32_t off = SW128(t * 128 + sq * 2);
            *(__half2*)(smem + PH + off)     = __halves2half2(hi[0], hi[1]);
            *(__half2*)(smem + PH + off + 4) = __halves2half2(hi[2], hi[3]);
            *(__half2*)(smem + PL + off)     = __halves2half2(lo[0], lo[1]);
            *(__half2*)(smem + PL + off + 4) = __halves2half2(lo[2], lo[3]);
        }
        load_tile256<64>(smem + VH, Vh + s0, Ll, tid);
        load_tile256<64>(smem + VL, Vl + s0, Ll, tid);
        __syncthreads();
        gemm_chunk<2, 4>(sb + VH, sb + VL, sb + PH, sb + PL,
                         wm * 32, wn * 32, lane, acc);
        __syncthreads();
    }

    float* ob = out + (size_t)bh * Dk * Ll;
    const int gid = lane >> 2, tid4 = lane & 3;
    #pragma unroll
    for (int mf = 0; mf < 2; mf++)
        #pragma unroll
        for (int h2 = 0; h2 < 2; h2++) {
            const int c = wm * 32 + mf * 16 + gid + h2 * 8;
            #pragma unroll
            for (int nf = 0; nf < 4; nf++) {
                const int t = t0 + wn * 32 + nf * 8 + tid4 * 2;
                float2 vv = make_float2(acc[mf][nf][h2 * 2],
                                        acc[mf][nf][h2 * 2 + 1]);
                *(float2*)(ob + (size_t)c * Ll + t) = vv;
            }
        }
}

// ---------------------------------------------------------------------------
extern "C" void kernel_launch(void* const* d_in, const int* in_sizes, int n_in,
                              void* d_out, int out_size) {
    const float* q  = (const float*)d_in[0];
    const float* k  = (const float*)d_in[1];
    const float* v  = (const float*)d_in[2];
    const float* Wq = (const float*)d_in[3];
    const float* bq = (const float*)d_in[4];
    const float* Wk = (const float*)d_in[5];
    const float* bk = (const float*)d_in[6];
    const float* Wv = (const float*)d_in[7];
    const float* bv = (const float*)d_in[8];
    float* out = (float*)d_out;

    cudaFuncSetAttribute(proj_mma,   cudaFuncAttributeMaxDynamicSharedMemorySize, 65536);
    cudaFuncSetAttribute(scores_mma, cudaFuncAttributeMaxDynamicSharedMemorySize, 65536);
    cudaFuncSetAttribute(out_mma,    cudaFuncAttributeMaxDynamicSharedMemorySize, 57344);

    conv_w_kernel<<<1024, 256>>>(Wq, 0);
    conv_w_kernel<<<1024, 256>>>(Wk, 1);
    conv_w_kernel<<<1024, 256>>>(Wv, 2);

    dim3 gt(32, 32, Bsz), bt(32, 8);
    dim3 gp(8, 8, Bsz);

    conv_xt_kernel<<<gt, bt>>>(q);
    proj_mma<<<gp, 256, 65536>>>(bq, 0);
    conv_xt_kernel<<<gt, bt>>>(k);
    proj_mma<<<gp, 256, 65536>>>(bk, 1);
    conv_xt_kernel<<<gt, bt>>>(v);
    proj_mma<<<gp, 256, 65536>>>(bv, 2);

    scores_mma<<<dim3(8, 8, NBH), 256, 65536>>>();
    stats_kernel<<<dim3(4, NBH), 256>>>();
    out_mma<<<dim3(8, NBH), 256, 57344>>>(out);
}